// round 3
// baseline (speedup 1.0000x reference)
#include <cuda_runtime.h>
#include <math.h>

#define NN 50000
#define EE 800000
#define DD 200
#define RR 230
#define NBLK ((NN + 255) / 256)   // 196 scan blocks

typedef unsigned long long ull;

// ---- scratch (__device__ globals; no allocations allowed) ----
__device__ __align__(128) float g_agg[NN * DD];   // gathered aggregation (pre-normalized)
__device__ __align__(128) float g_h1[NN * DD];    // layer-1 output
__device__ __align__(128) float g_norm[NN];       // 1/deg (0 if deg==0)
__device__ __align__(128) int   g_deg[NN];
__device__ __align__(128) int   g_rowoff[NN];     // exclusive prefix within scan block
__device__ __align__(128) int   g_blksum[NBLK];
__device__ __align__(128) int   g_blkpref[NBLK];
__device__ __align__(128) int   g_rowptr[NN + 1];
__device__ __align__(128) int   g_cursor[NN];
__device__ __align__(128) int   g_epk[EE];        // packed (etype<<16 | src)
__device__ __align__(128) float g_WtA[DD * DD];   // W_ih^T (k-major)
__device__ __align__(128) float g_WtB[DD * DD];   // W_hh^T (k-major)
__device__ __align__(128) float g_Mt[DD * DD];    // lw2 @ W_ih^T (k-major)
__device__ __align__(128) float g_bfin[DD];       // bih + bhh + b2 @ W_ih^T

// ---- f32x2 helpers ----
__device__ __forceinline__ ull fpack(float x, float y) {
    ull v; asm("mov.b64 %0, {%1, %2};" : "=l"(v) : "f"(x), "f"(y)); return v;
}
__device__ __forceinline__ float2 funpack(ull v) {
    float2 f; asm("mov.b64 {%0, %1}, %2;" : "=f"(f.x), "=f"(f.y) : "l"(v)); return f;
}
__device__ __forceinline__ void fma2(ull& acc, ull a, ull w) {
    asm("fma.rn.f32x2 %0, %1, %2, %0;" : "+l"(acc) : "l"(a), "l"(w));
}

// ================= CSR build =================
__global__ void deg_kernel(const int* __restrict__ dst) {
    int e = blockIdx.x * blockDim.x + threadIdx.x;
    if (e < EE) atomicAdd(&g_deg[dst[e]], 1);
}

__global__ void scan_block_kernel() {
    __shared__ int sh[256];
    int tid = threadIdx.x;
    int n = blockIdx.x * 256 + tid;
    int v = (n < NN) ? g_deg[n] : 0;
    sh[tid] = v;
    __syncthreads();
#pragma unroll
    for (int off = 1; off < 256; off <<= 1) {
        int t = (tid >= off) ? sh[tid - off] : 0;
        __syncthreads();
        sh[tid] += t;
        __syncthreads();
    }
    if (n < NN) g_rowoff[n] = sh[tid] - v;   // exclusive
    if (tid == 255) g_blksum[blockIdx.x] = sh[255];
}

__global__ void scan_top_kernel() {
    __shared__ int sh[256];
    int tid = threadIdx.x;
    int v = (tid < NBLK) ? g_blksum[tid] : 0;
    sh[tid] = v;
    __syncthreads();
#pragma unroll
    for (int off = 1; off < 256; off <<= 1) {
        int t = (tid >= off) ? sh[tid - off] : 0;
        __syncthreads();
        sh[tid] += t;
        __syncthreads();
    }
    if (tid < NBLK) g_blkpref[tid] = sh[tid] - v;
}

__global__ void scan_fin_kernel() {
    int n = blockIdx.x * blockDim.x + threadIdx.x;
    if (n < NN) {
        int rp = g_rowoff[n] + g_blkpref[n >> 8];
        g_rowptr[n] = rp;
        g_cursor[n] = rp;
        int d = g_deg[n];
        g_norm[n] = (d > 0) ? (1.0f / (float)d) : 0.0f;
    }
    if (n == 0) g_rowptr[NN] = EE;
}

__global__ void fill_kernel(const int* __restrict__ src,
                            const int* __restrict__ dst,
                            const int* __restrict__ et) {
    int e = blockIdx.x * blockDim.x + threadIdx.x;
    if (e >= EE) return;
    int n = dst[e];
    int pos = atomicAdd(&g_cursor[n], 1);
    g_epk[pos] = (et[e] << 16) | src[e];
}

// ================= gather aggregation =================
// One warp per node. Lanes 0..24 each own an 8-float output chunk (=4 S=2 blocks).
// Reads x[src] rows + w[etype] rows (coalesced), accumulates in registers,
// writes agg[n,:] * norm[n] once. No atomics, no memset needed.
__global__ void gather_kernel(const float* __restrict__ x,
                              const float* __restrict__ w) {
    int gw = (blockIdx.x * blockDim.x + threadIdx.x) >> 5;   // node id
    int lane = threadIdx.x & 31;
    if (gw >= NN || lane >= 25) return;
    int c = lane;

    int rp0 = g_rowptr[gw];
    int rp1 = g_rowptr[gw + 1];
    float nv = g_norm[gw];

    float a0 = 0.f, a1 = 0.f, a2 = 0.f, a3 = 0.f;
    float a4 = 0.f, a5 = 0.f, a6 = 0.f, a7 = 0.f;

#define EDGE_BODY(i)                                                          \
    {                                                                         \
        int pk = __ldg(&g_epk[i]);                                            \
        int s = pk & 0xffff;                                                  \
        int r = pk >> 16;                                                     \
        const float4* xp = (const float4*)(x + s * DD) + 2 * c;               \
        float4 x0 = xp[0], x1 = xp[1];                                        \
        const float4* wp = (const float4*)(w + r * 400) + 4 * c;              \
        float4 q0 = wp[0], q1 = wp[1], q2 = wp[2], q3 = wp[3];                \
        a0 += x0.x * q0.x + x0.y * q0.z;                                      \
        a1 += x0.x * q0.y + x0.y * q0.w;                                      \
        a2 += x0.z * q1.x + x0.w * q1.z;                                      \
        a3 += x0.z * q1.y + x0.w * q1.w;                                      \
        a4 += x1.x * q2.x + x1.y * q2.z;                                      \
        a5 += x1.x * q2.y + x1.y * q2.w;                                      \
        a6 += x1.z * q3.x + x1.w * q3.z;                                      \
        a7 += x1.z * q3.y + x1.w * q3.w;                                      \
    }

    int i = rp0;
    for (; i + 1 < rp1; i += 2) { EDGE_BODY(i); EDGE_BODY(i + 1); }
    if (i < rp1) EDGE_BODY(i);
#undef EDGE_BODY

    float4* op = (float4*)(g_agg + gw * DD) + 2 * c;
    op[0] = make_float4(a0 * nv, a1 * nv, a2 * nv, a3 * nv);
    op[1] = make_float4(a4 * nv, a5 * nv, a6 * nv, a7 * nv);
}

// ================= weight prep =================
__global__ void transpose_kernel(const float* __restrict__ A, const float* __restrict__ B) {
    int idx = blockIdx.x * blockDim.x + threadIdx.x;
    if (idx < DD * DD) {
        int j = idx / DD, k = idx - j * DD;
        g_WtA[k * DD + j] = A[idx];
        g_WtB[k * DD + j] = B[idx];
    }
}

// Mt[t,j] = sum_u lw2[t,u] * WtA[u,j]   (one block per t-row; coalesced in j)
__global__ void mt_kernel(const float* __restrict__ lw2) {
    __shared__ float row[DD];
    int t = blockIdx.x;
    for (int i = threadIdx.x; i < DD; i += 256) row[i] = lw2[t * DD + i];
    __syncthreads();
    int j = threadIdx.x;
    if (j >= DD) return;
    float s = 0.0f;
#pragma unroll 4
    for (int u = 0; u < DD; u++) s += row[u] * g_WtA[u * DD + j];
    g_Mt[t * DD + j] = s;
}

// bfin[j] = bih[j] + bhh[j] + sum_t b2[t] * WtA[t,j]
__global__ void bias_kernel(const float* __restrict__ b2,
                            const float* __restrict__ bih,
                            const float* __restrict__ bhh) {
    __shared__ float b2s[DD];
    for (int i = threadIdx.x; i < DD; i += 256) b2s[i] = b2[i];
    __syncthreads();
    int j = threadIdx.x;
    if (j >= DD) return;
    float s = bih[j] + bhh[j];
#pragma unroll 4
    for (int t = 0; t < DD; t++) s += b2s[t] * g_WtA[t * DD + j];
    g_bfin[j] = s;
}

// ================= f32x2 GEMM (full-width, 64 x 200 tiles) =================
// out[n,j] = act( sum_p sum_k A_p[n,k]*W_p[k,j]  (+ agg[n,j]) + bias[j] )
// blockDim (8,32). tx covers col quads {(tx+8j)*4 : j<6} + col 192+tx.
// ty covers rows ty, ty+32. KT=20. A stored duplicated ({a,a} pairs) in smem
// so one LDS.64 feeds fma.rn.f32x2 directly; W pairs load via 16B smem loads.
template <int NPASS, bool TANH, bool HAS_AGG>
__global__ __launch_bounds__(256, 2) void gemm200(
    const float* __restrict__ A0, const float* __restrict__ W0,
    const float* __restrict__ A1, const float* __restrict__ W1,
    const float* __restrict__ A2, const float* __restrict__ W2,
    const float* __restrict__ bias, float* __restrict__ out) {
    __shared__ float Ws[20 * 200];
    __shared__ ull Asd[64 * 22];   // duplicated pairs, stride 22 (pad)

    int tx = threadIdx.x;          // 0..7
    int ty = threadIdx.y;          // 0..31
    int tid = ty * 8 + tx;
    int row0 = blockIdx.x * 64;

    ull acc[2][6][2];
    float acce0 = 0.0f, acce1 = 0.0f;
#pragma unroll
    for (int m = 0; m < 2; m++)
#pragma unroll
        for (int j = 0; j < 6; j++) { acc[m][j][0] = 0ull; acc[m][j][1] = 0ull; }

#pragma unroll
    for (int p = 0; p < NPASS; p++) {
        const float* A = (p == 0) ? A0 : ((p == 1) ? A1 : A2);
        const float* W = (p == 0) ? W0 : ((p == 1) ? W1 : W2);
        for (int kb = 0; kb < DD; kb += 20) {
            __syncthreads();
            // W tile: 20 x 200 = 1000 float4
            for (int i = tid; i < 1000; i += 256) {
                int k = i / 50, c4 = i - k * 50;
                ((float4*)(Ws + k * 200))[c4] = ((const float4*)(W + (kb + k) * DD))[c4];
            }
            // A tile: 64 rows x 20 cols = 320 float4, stored as duplicated pairs
            for (int i = tid; i < 320; i += 256) {
                int rr = i / 5, c4 = i - rr * 5;
                int gr = row0 + rr;
                float4 v = make_float4(0.f, 0.f, 0.f, 0.f);
                if (gr < NN) v = ((const float4*)(A + gr * DD + kb))[c4];
                ull* ap = Asd + rr * 22 + c4 * 4;
                ap[0] = fpack(v.x, v.x);
                ap[1] = fpack(v.y, v.y);
                ap[2] = fpack(v.z, v.z);
                ap[3] = fpack(v.w, v.w);
            }
            __syncthreads();
#pragma unroll
            for (int k = 0; k < 20; k++) {
                ull ap0 = Asd[ty * 22 + k];
                ull ap1 = Asd[(ty + 32) * 22 + k];
                float we = Ws[k * 200 + 192 + tx];
                acce0 += funpack(ap0).x * we;
                acce1 += funpack(ap1).x * we;
#pragma unroll
                for (int j = 0; j < 6; j++) {
                    ulonglong2 wp = *(const ulonglong2*)(Ws + k * 200 + (tx + 8 * j) * 4);
                    fma2(acc[0][j][0], ap0, wp.x);
                    fma2(acc[0][j][1], ap0, wp.y);
                    fma2(acc[1][j][0], ap1, wp.x);
                    fma2(acc[1][j][1], ap1, wp.y);
                }
            }
        }
    }

    // epilogue
#pragma unroll
    for (int m = 0; m < 2; m++) {
        int gr = row0 + ty + m * 32;
        if (gr >= NN) continue;
#pragma unroll
        for (int j = 0; j < 6; j++) {
            int col = (tx + 8 * j) * 4;
            float2 lo = funpack(acc[m][j][0]);
            float2 hi = funpack(acc[m][j][1]);
            float4 v = make_float4(lo.x, lo.y, hi.x, hi.y);
            if (HAS_AGG) {
                float4 a = *(const float4*)(g_agg + gr * DD + col);
                v.x += a.x; v.y += a.y; v.z += a.z; v.w += a.w;
            }
            float4 bb = *(const float4*)(bias + col);
            v.x += bb.x; v.y += bb.y; v.z += bb.z; v.w += bb.w;
            if (TANH) { v.x = tanhf(v.x); v.y = tanhf(v.y); v.z = tanhf(v.z); v.w = tanhf(v.w); }
            *(float4*)(out + gr * DD + col) = v;
        }
        int col = 192 + tx;
        float v = m ? acce1 : acce0;
        if (HAS_AGG) v += g_agg[gr * DD + col];
        v += bias[col];
        if (TANH) v = tanhf(v);
        out[gr * DD + col] = v;
    }
}

// ================= launch =================
extern "C" void kernel_launch(void* const* d_in, const int* in_sizes, int n_in,
                              void* d_out, int out_size) {
    const float* node_feat = (const float*)d_in[0];
    const float* dyn       = (const float*)d_in[1];   // (N,1,D) contiguous = h0
    const int*   src       = (const int*)d_in[2];
    const int*   dst       = (const int*)d_in[3];
    const int*   et        = (const int*)d_in[4];
    const float* w1        = (const float*)d_in[5];
    const float* lw1       = (const float*)d_in[6];
    const float* b1        = (const float*)d_in[7];
    const float* w2        = (const float*)d_in[8];
    const float* lw2       = (const float*)d_in[9];
    const float* b2        = (const float*)d_in[10];
    const float* Wih       = (const float*)d_in[11];
    const float* Whh       = (const float*)d_in[12];
    const float* bih       = (const float*)d_in[13];
    const float* bhh       = (const float*)d_in[14];
    float* out = (float*)d_out;

    void *agg_p, *h1_p, *deg_p, *wta_p, *wtb_p, *mt_p, *bfin_p;
    cudaGetSymbolAddress(&agg_p, g_agg);
    cudaGetSymbolAddress(&h1_p, g_h1);
    cudaGetSymbolAddress(&deg_p, g_deg);
    cudaGetSymbolAddress(&wta_p, g_WtA);
    cudaGetSymbolAddress(&wtb_p, g_WtB);
    cudaGetSymbolAddress(&mt_p, g_Mt);
    cudaGetSymbolAddress(&bfin_p, g_bfin);

    // CSR build
    cudaMemsetAsync(deg_p, 0, sizeof(int) * NN);
    deg_kernel<<<(EE + 255) / 256, 256>>>(dst);
    scan_block_kernel<<<NBLK, 256>>>();
    scan_top_kernel<<<1, 256>>>();
    scan_fin_kernel<<<NBLK, 256>>>();
    fill_kernel<<<(EE + 255) / 256, 256>>>(src, dst, et);

    // weight prep
    transpose_kernel<<<(DD * DD + 255) / 256, 256>>>(Wih, Whh);
    mt_kernel<<<DD, 256>>>(lw2);
    bias_kernel<<<1, 256>>>(b2, bih, bhh);

    const int gthreads = NN * 32;                 // one warp per node
    const int gblocks = (gthreads + 255) / 256;   // 6250
    dim3 gemm_blk(8, 32);
    int gemm_grd = (NN + 63) / 64;                // 782

    // layer 1: gather (pre-normalized), then h1 = tanh(x@lw1 + agg1 + b1)
    gather_kernel<<<gblocks, 256>>>(node_feat, w1);
    gemm200<1, true, true><<<gemm_grd, gemm_blk>>>(
        node_feat, lw1, nullptr, nullptr, nullptr, nullptr, b1, (float*)h1_p);

    // layer 2: gather from h1
    gather_kernel<<<gblocks, 256>>>((const float*)h1_p, w2);

    // fused final: out = tanh( agg2@Wih^T + h1@(lw2@Wih^T) + h0@Whh^T + bfin )
    gemm200<3, true, false><<<gemm_grd, gemm_blk>>>(
        (const float*)agg_p, (const float*)wta_p,
        (const float*)h1_p,  (const float*)mt_p,
        dyn,                 (const float*)wtb_p,
        (const float*)bfin_p, out);
}